// round 8
// baseline (speedup 1.0000x reference)
#include <cuda_runtime.h>
#include <cstdint>

// out[i, h=n*7+o, m] = sum_{j<48,k<3} W[i,j*3+k] * x[j, n*7+(o+k-1), m]
//   (term dropped when o+k-1 outside [0,7))
// x: (48,56,56) f32   W: (192,48,3) f32   out: (192,56,56) f32

#define JCH 48
#define KTAP 3
#define MW 56
#define MP 64            // padded m (float4-friendly)
#define BI 24            // output channels per block -> grid (56,8)=448 = 3.03/SM
#define WSS 28           // ws row stride (mult of 4 -> aligned f4; 4-way STS conflicts max)
#define NTHREADS 96

__device__ __forceinline__ uint32_t smem_u32(const void* p) {
    uint32_t a;
    asm("{ .reg .u64 t; cvta.to.shared.u64 t, %1; cvt.u32.u64 %0, t; }" : "=r"(a) : "l"(p));
    return a;
}
#define CP_ASYNC16(dst, src, nbytes) \
    asm volatile("cp.async.ca.shared.global [%0], [%1], 16, %2;" \
                 :: "r"(dst), "l"(src), "r"(nbytes))
#define CP_ASYNC_COMMIT() asm volatile("cp.async.commit_group;")
#define CP_ASYNC_WAIT0()  asm volatile("cp.async.wait_group 0;")

__global__ __launch_bounds__(NTHREADS)
void fold_conv_kernel(const float* __restrict__ x,
                      const float* __restrict__ W,
                      float* __restrict__ out)
{
    extern __shared__ float sm[];
    float* xs = sm;                         // [KTAP*JCH][MP]  = 144*64 floats (36 KB)
    float* ws = sm + KTAP * JCH * MP;       // [JCH*KTAP][WSS] = 144*28 floats (15.75 KB)

    const int tid = threadIdx.x;
    const int h  = blockIdx.x;              // 0..55
    const int n  = h / 7;
    const int o  = h - n * 7;
    const int i0 = blockIdx.y * BI;         // 0..168 step 24

    // ---- x slab via cp.async: 144 rows x 16 f4 (14 real + 2 pad), zero-filled ----
    {
        const uint32_t xs_b = smem_u32(xs);
        #pragma unroll
        for (int it = 0; it < (KTAP * JCH * 16) / NTHREADS; ++it) {   // 24 iters
            int idx = tid + it * NTHREADS;          // 0..2303
            int row = idx >> 4;                     // k*48+j
            int s   = idx & 15;                     // f4 slot
            int k   = row / JCH;
            int j   = row - k * JCH;
            int r   = o + k - 1;
            bool valid = (r >= 0) && (r < 7) && (s < 14);
            const float* src = valid ? &x[(j * 56 + n * 7 + r) * 56 + s * 4] : x;
            CP_ASYNC16(xs_b + (uint32_t)idx * 16u, src, valid ? 16 : 0);
        }
        CP_ASYNC_COMMIT();
    }
    // ---- W tile: coalesced scalar LDG (jk-contiguous), STS to [jk][ii] ----
    #pragma unroll
    for (int it = 0; it < (BI * JCH * KTAP) / NTHREADS; ++it) {       // 36 iters
        int idx = tid + it * NTHREADS;              // 0..3455
        int ii  = idx / (JCH * KTAP);
        int jk  = idx - ii * (JCH * KTAP);
        ws[jk * WSS + ii] = W[(i0 + ii) * (JCH * KTAP) + jk];
    }
    CP_ASYNC_WAIT0();
    __syncthreads();

    // ---- register-tiled mainloop: each thread computes 4i x 4m ----
    const int mg  = tid & 15;               // 16 m-groups (14,15 hit padding, discarded)
    const int ig  = tid >> 4;               // 6 i-groups
    const int m0  = mg * 4;
    const int ii0 = ig * 4;

    float acc[4][4];
    #pragma unroll
    for (int a = 0; a < 4; ++a)
        #pragma unroll
        for (int b = 0; b < 4; ++b)
            acc[a][b] = 0.0f;

    #pragma unroll 4
    for (int j = 0; j < JCH; ++j) {
        float4 xv[KTAP];
        float4 wv[KTAP];
        #pragma unroll
        for (int k = 0; k < KTAP; ++k) {
            xv[k] = *(const float4*)&xs[(k * JCH + j) * MP + m0];
            wv[k] = *(const float4*)&ws[(j * 3 + k) * WSS + ii0];
        }
        #pragma unroll
        for (int k = 0; k < KTAP; ++k) {
            const float wr[4] = {wv[k].x, wv[k].y, wv[k].z, wv[k].w};
            const float xr[4] = {xv[k].x, xv[k].y, xv[k].z, xv[k].w};
            #pragma unroll
            for (int a = 0; a < 4; ++a) {
                acc[a][0] = fmaf(wr[a], xr[0], acc[a][0]);
                acc[a][1] = fmaf(wr[a], xr[1], acc[a][1]);
                acc[a][2] = fmaf(wr[a], xr[2], acc[a][2]);
                acc[a][3] = fmaf(wr[a], xr[3], acc[a][3]);
            }
        }
    }

    // ---- store (skip padded m-groups; 16B-aligned float4) ----
    if (m0 < MW) {
        #pragma unroll
        for (int a = 0; a < 4; ++a) {
            const int i = i0 + ii0 + a;
            float4 v = {acc[a][0], acc[a][1], acc[a][2], acc[a][3]};
            *(float4*)&out[i * 3136 + h * 56 + m0] = v;
        }
    }
}

extern "C" void kernel_launch(void* const* d_in, const int* in_sizes, int n_in,
                              void* d_out, int out_size)
{
    const float* x = (const float*)d_in[0];   // 48*56*56
    const float* W = (const float*)d_in[1];   // 192*48*3
    float* out = (float*)d_out;               // 192*56*56

    const int smem = (KTAP * JCH * MP + JCH * KTAP * WSS) * (int)sizeof(float); // 52992 B
    static bool attr_set = false;
    if (!attr_set) {
        cudaFuncSetAttribute(fold_conv_kernel,
                             cudaFuncAttributeMaxDynamicSharedMemorySize, smem);
        attr_set = true;
    }
    dim3 grid(56, 8);
    fold_conv_kernel<<<grid, NTHREADS, smem>>>(x, W, out);
}

// round 9
// speedup vs baseline: 1.1065x; 1.1065x over previous
#include <cuda_runtime.h>

// out[i, h=n*7+o, m] = sum_{j<48,k<3} W[i,j*3+k] * x[j, n*7+(o+k-1), m]
//   (term dropped when o+k-1 outside [0,7))
// x: (48,56,56) f32   W: (192,48,3) f32   out: (192,56,56) f32

#define JCH 48
#define KTAP 3
#define MW 56
#define MP 64            // padded m (float4-friendly)
#define BI 32            // output channels per block
#define WSS 36           // ws row stride, multiple of 4 -> 16B-aligned float4 loads
#define NTHREADS 128

__global__ __launch_bounds__(NTHREADS)
void fold_conv_kernel(const float* __restrict__ x,
                      const float* __restrict__ W,
                      float* __restrict__ out)
{
    extern __shared__ float sm[];
    float* xs = sm;                         // [KTAP*JCH][MP]  = 144*64 floats (36 KB)
    float* ws = sm + KTAP * JCH * MP;       // [JCH*KTAP][WSS] = 144*36 floats (20.25 KB)

    const int tid = threadIdx.x;
    const int h  = blockIdx.x;              // 0..55
    const int n  = h / 7;
    const int o  = h - n * 7;
    const int i0 = blockIdx.y * BI;         // 0..160 step 32

    // ---- load x slab: 144 rows x 16 float4, coalesced, zero-padded ----
    {
        float4* xs4 = (float4*)xs;
        #pragma unroll
        for (int it = 0; it < (KTAP * JCH * 16) / NTHREADS; ++it) {   // 18 iters
            int idx = tid + it * NTHREADS;          // 0..2303
            int row = idx >> 4;                     // k*48+j
            int s   = idx & 15;                     // float4 slot
            int k   = row / JCH;
            int j   = row - k * JCH;
            int r   = o + k - 1;
            float4 v = make_float4(0.f, 0.f, 0.f, 0.f);
            if (r >= 0 && r < 7 && s < 14)
                v = *(const float4*)&x[(j * 56 + n * 7 + r) * 56 + s * 4];
            xs4[idx] = v;
        }
    }
    // ---- load W tile: f4 gmem reads (coalesced), transposed scatter [jk][ii] ----
    #pragma unroll
    for (int it = 0; it < (BI * 36) / NTHREADS; ++it) {               // 9 iters
        int idx = tid + it * NTHREADS;              // 0..1151 (f4 chunks)
        int ii  = idx / 36;
        int q   = idx - ii * 36;                    // f4 slot within 144
        float4 v = *(const float4*)&W[(i0 + ii) * (JCH * KTAP) + q * 4];
        ws[(q * 4 + 0) * WSS + ii] = v.x;
        ws[(q * 4 + 1) * WSS + ii] = v.y;
        ws[(q * 4 + 2) * WSS + ii] = v.z;
        ws[(q * 4 + 3) * WSS + ii] = v.w;
    }
    __syncthreads();

    // ---- register-tiled mainloop: 4i x 4m per thread, double-buffered ----
    const int mg  = tid & 15;               // m fastest -> coalesced stores
    const int ig  = tid >> 4;               // 8 i-groups
    const int m0  = mg * 4;                 // mg 14,15 hit padding (discarded)
    const int ii0 = ig * 4;

    float acc[4][4];
    #pragma unroll
    for (int a = 0; a < 4; ++a)
        #pragma unroll
        for (int b = 0; b < 4; ++b)
            acc[a][b] = 0.0f;

    const float* xp = xs + m0;              // +64 per j; tap offset k*JCH*MP
    const float* wp = ws + ii0;             // +3*WSS per j; tap offset k*WSS

    float4 xv[2][KTAP];
    float4 wv[2][KTAP];
    #pragma unroll
    for (int k = 0; k < KTAP; ++k) {        // prefetch j=0
        xv[0][k] = *(const float4*)(xp + k * (JCH * MP));
        wv[0][k] = *(const float4*)(wp + k * WSS);
    }

    #pragma unroll 2
    for (int j = 0; j < JCH; ++j) {
        const int cur = j & 1;
        const int nxt = cur ^ 1;
        if (j + 1 < JCH) {                  // prefetch j+1 while computing j
            const float* xq = xp + 64;
            const float* wq = wp + 3 * WSS;
            #pragma unroll
            for (int k = 0; k < KTAP; ++k) {
                xv[nxt][k] = *(const float4*)(xq + k * (JCH * MP));
                wv[nxt][k] = *(const float4*)(wq + k * WSS);
            }
        }
        #pragma unroll
        for (int k = 0; k < KTAP; ++k) {
            const float wr[4] = {wv[cur][k].x, wv[cur][k].y, wv[cur][k].z, wv[cur][k].w};
            const float xr[4] = {xv[cur][k].x, xv[cur][k].y, xv[cur][k].z, xv[cur][k].w};
            #pragma unroll
            for (int a = 0; a < 4; ++a) {
                acc[a][0] = fmaf(wr[a], xr[0], acc[a][0]);
                acc[a][1] = fmaf(wr[a], xr[1], acc[a][1]);
                acc[a][2] = fmaf(wr[a], xr[2], acc[a][2]);
                acc[a][3] = fmaf(wr[a], xr[3], acc[a][3]);
            }
        }
        xp += MP;
        wp += 3 * WSS;
    }

    // ---- store (skip padded m-groups; 16B-aligned float4) ----
    if (m0 < MW) {
        #pragma unroll
        for (int a = 0; a < 4; ++a) {
            const int i = i0 + ii0 + a;
            float4 v = {acc[a][0], acc[a][1], acc[a][2], acc[a][3]};
            *(float4*)&out[i * 3136 + h * 56 + m0] = v;
        }
    }
}

extern "C" void kernel_launch(void* const* d_in, const int* in_sizes, int n_in,
                              void* d_out, int out_size)
{
    const float* x = (const float*)d_in[0];   // 48*56*56
    const float* W = (const float*)d_in[1];   // 192*48*3
    float* out = (float*)d_out;               // 192*56*56

    const int smem = (KTAP * JCH * MP + JCH * KTAP * WSS) * (int)sizeof(float); // 57600 B
    static bool attr_set = false;
    if (!attr_set) {
        cudaFuncSetAttribute(fold_conv_kernel,
                             cudaFuncAttributeMaxDynamicSharedMemorySize, smem);
        attr_set = true;
    }
    dim3 grid(56, 6);
    fold_conv_kernel<<<grid, NTHREADS, smem>>>(x, W, out);
}